// round 1
// baseline (speedup 1.0000x reference)
#include <cuda_runtime.h>
#include <cstdint>

#define NB      16      // batch elements per CTA
#define WDIM    256
#define HDIM    256
#define DPT     8
#define CHUNK   32      // h-columns per smem chunk
#define NCHUNK  (HDIM / CHUNK)          // 8
#define TILE_FLOATS (WDIM * CHUNK)      // 8192 floats per array per chunk
#define BUF_BYTES   (2 * TILE_FLOATS * 4)   // m + b per buffer = 64 KB
#define SMEM_BYTES  (2 * BUF_BYTES)         // double buffered = 128 KB

__device__ __forceinline__ void cp_async16(uint32_t smem_addr, const void* gptr) {
    asm volatile("cp.async.cg.shared.global [%0], [%1], 16;\n"
                 :: "r"(smem_addr), "l"(gptr));
}
__device__ __forceinline__ void cp_commit() {
    asm volatile("cp.async.commit_group;\n");
}

__global__ __launch_bounds__(256, 1)
void dpm_kernel(const float* __restrict__ val,
                const float* __restrict__ M1, const float* __restrict__ B1,
                const float* __restrict__ M2, const float* __restrict__ B2,
                float* __restrict__ out)
{
    extern __shared__ float smem[];
    __shared__ float red[8][NB];
    __shared__ float q_s[NB];

    const int tid    = threadIdx.x;
    const int batch0 = blockIdx.x * NB;
    const int branch = blockIdx.y;

    const float* __restrict__ Mb = branch ? M2 : M1;
    const float* __restrict__ Bb = branch ? B2 : B1;

    const uint32_t sbase = (uint32_t)__cvta_generic_to_shared(smem);

    float q[NB];
#pragma unroll
    for (int i = 0; i < NB; i++) q[i] = val[batch0 + i];

    // Issue one chunk (both M and B slices) into buffer `buf` as one commit group.
    auto issue = [&](int d, int c, int buf) {
        const float* mp = Mb + d * (WDIM * HDIM);
        const float* bp = Bb + d * (WDIM * HDIM);
        const int hc = c * CHUNK;
        const uint32_t so_m = sbase + buf * BUF_BYTES;
        const uint32_t so_b = so_m + TILE_FLOATS * 4;
#pragma unroll
        for (int i = 0; i < (TILE_FLOATS / 4) / 256; i++) {   // 8 float4 per thread
            const int e4   = i * 256 + tid;
            const int row  = e4 >> 3;       // 8 float4 per 32-col row
            const int c4   = e4 & 7;
            const int goff = row * HDIM + hc + c4 * 4;        // floats
            const int soff = (row * CHUNK + c4 * 4) * 4;      // bytes
            cp_async16(so_m + soff, mp + goff);
            cp_async16(so_b + soff, bp + goff);
        }
        cp_commit();
    };

    // Prologue: prefetch chunk (d=0, c=0) into buffer 0.
    issue(0, 0, 0);
    int buf = 0;

    for (int d = 0; d < DPT; d++) {
        float acc[NB];
#pragma unroll
        for (int i = 0; i < NB; i++) acc[i] = __int_as_float(0xff800000); // -inf

        for (int c = 0; c < NCHUNK; c++) {
            const bool has_next = !(d == DPT - 1 && c == NCHUNK - 1);
            if (has_next) {
                int nd = d, nc = c + 1;
                if (nc == NCHUNK) { nc = 0; nd = d + 1; }
                issue(nd, nc, buf ^ 1);
                asm volatile("cp.async.wait_group 1;\n");
            } else {
                asm volatile("cp.async.wait_group 0;\n");
            }
            __syncthreads();

            // Compute on `buf`: thread tid owns row w=tid; lane-rotated column
            // order makes the scalar LDS conflict-free with zero padding.
            const float* sm_m = smem + buf * (2 * TILE_FLOATS) + tid * CHUNK;
            const float* sm_b = sm_m + TILE_FLOATS;
#pragma unroll 4
            for (int cc = 0; cc < CHUNK; cc++) {
                const int col = (cc + tid) & (CHUNK - 1);
                const float m = sm_m[col];
                const float b = sm_b[col];
#pragma unroll
                for (int i = 0; i < NB; i++)
                    acc[i] = fmaxf(acc[i], fmaf(q[i], m, b));
            }
            __syncthreads();   // all reads done before this buffer is refilled
            buf ^= 1;
        }

        // min over w (256 threads): warp shfl-min, then cross-warp via smem.
#pragma unroll
        for (int i = 0; i < NB; i++) {
            float v = acc[i];
#pragma unroll
            for (int o = 16; o > 0; o >>= 1)
                v = fminf(v, __shfl_xor_sync(0xffffffffu, v, o));
            if ((tid & 31) == 0) red[tid >> 5][i] = v;
        }
        __syncthreads();
        if (tid < NB) {
            float v = red[0][tid];
#pragma unroll
            for (int w = 1; w < 8; w++) v = fminf(v, red[w][tid]);
            q_s[tid] = v;
        }
        __syncthreads();
#pragma unroll
        for (int i = 0; i < NB; i++) q[i] = q_s[i];
    }

    if (tid < NB)
        out[branch * 1024 + batch0 + tid] = q_s[tid];
}

extern "C" void kernel_launch(void* const* d_in, const int* in_sizes, int n_in,
                              void* d_out, int out_size)
{
    const float* val = (const float*)d_in[0];
    const float* M1  = (const float*)d_in[1];
    const float* B1  = (const float*)d_in[2];
    const float* M2  = (const float*)d_in[3];
    const float* B2  = (const float*)d_in[4];
    float* out = (float*)d_out;

    cudaFuncSetAttribute(dpm_kernel,
                         cudaFuncAttributeMaxDynamicSharedMemorySize, SMEM_BYTES);

    dim3 grid(1024 / NB, 2);   // 64 batch tiles x 2 branches = 128 CTAs
    dpm_kernel<<<grid, 256, SMEM_BYTES>>>(val, M1, B1, M2, B2, out);
}

// round 2
// speedup vs baseline: 1.2056x; 1.2056x over previous
#include <cuda_runtime.h>
#include <cstdint>

#define NB      16                       // batch elements per CTA
#define WDIM    256
#define HDIM    256
#define DPT     8
#define CHUNK   32                       // h-columns per chunk
#define NCHUNK  (HDIM / CHUNK)           // 8
// Per-warp slice: m[32][32] + b[32][32] floats = 2048 floats (8KB) per buffer
#define WARP_BUF_FLOATS  2048
#define WARP_FLOATS      (2 * WARP_BUF_FLOATS)      // double buffered = 4096
#define SMEM_BYTES       (8 * WARP_FLOATS * 4)      // 8 warps = 128 KB

typedef unsigned long long u64;

__device__ __forceinline__ void cp_async16(uint32_t smem_addr, const void* gptr) {
    asm volatile("cp.async.cg.shared.global [%0], [%1], 16;\n"
                 :: "r"(smem_addr), "l"(gptr));
}
__device__ __forceinline__ void cp_commit() {
    asm volatile("cp.async.commit_group;\n");
}
__device__ __forceinline__ u64 pack_dup(float x) {
    u64 r;
    asm("mov.b64 %0, {%1, %1};" : "=l"(r) : "f"(x));
    return r;
}
__device__ __forceinline__ u64 ffma2(u64 a, u64 b, u64 c) {
    u64 d;
    asm("fma.rn.f32x2 %0, %1, %2, %3;" : "=l"(d) : "l"(a), "l"(b), "l"(c));
    return d;
}
__device__ __forceinline__ float unpack_lo(u64 v) {
    float lo, hi;
    asm("mov.b64 {%0, %1}, %2;" : "=f"(lo), "=f"(hi) : "l"(v));
    return lo;
}
__device__ __forceinline__ void unpack2(u64 v, float& lo, float& hi) {
    asm("mov.b64 {%0, %1}, %2;" : "=f"(lo), "=f"(hi) : "l"(v));
}
__device__ __forceinline__ void lds_v2b64(uint32_t addr, u64& a, u64& b) {
    asm volatile("ld.shared.v2.b64 {%0, %1}, [%2];" : "=l"(a), "=l"(b) : "r"(addr));
}

__global__ __launch_bounds__(256, 1)
void dpm_kernel(const float* __restrict__ val,
                const float* __restrict__ M1, const float* __restrict__ B1,
                const float* __restrict__ M2, const float* __restrict__ B2,
                float* __restrict__ out)
{
    extern __shared__ float smem[];
    __shared__ float red[8][NB];
    __shared__ float q_s[NB];

    const int tid    = threadIdx.x;
    const int wid    = tid >> 5;
    const int lane   = tid & 31;
    const int batch0 = blockIdx.x * NB;
    const int branch = blockIdx.y;

    const float* __restrict__ Mb = branch ? M2 : M1;
    const float* __restrict__ Bb = branch ? B2 : B1;

    // Per-warp smem slice base (bytes)
    const uint32_t sbase  = (uint32_t)__cvta_generic_to_shared(smem);
    const uint32_t wslice = sbase + wid * (WARP_FLOATS * 4);

    // This thread's row within the full W dimension
    const int row = wid * 32 + lane;

    u64 qq[NB];     // (q_i, q_i) packed
#pragma unroll
    for (int i = 0; i < NB; i++) qq[i] = pack_dup(val[batch0 + i]);

    // Issue one chunk (m + b slices for this warp's 32 rows) into buffer `buf`.
    auto issue = [&](int d, int c, int buf) {
        const float* mp = Mb + d * (WDIM * HDIM) + wid * 32 * HDIM + c * CHUNK;
        const float* bp = Bb + d * (WDIM * HDIM) + wid * 32 * HDIM + c * CHUNK;
        const uint32_t so_m = wslice + buf * (WARP_BUF_FLOATS * 4);
        const uint32_t so_b = so_m + 1024 * 4;
#pragma unroll
        for (int i = 0; i < 8; i++) {      // 8 float4 per thread for m, 8 for b
            const int e4 = i * 32 + lane;  // 0..255 across warp
            const int r  = e4 >> 3;        // 8 float4 per 32-col row
            const int c4 = e4 & 7;
            const int goff = r * HDIM + c4 * 4;            // floats
            const uint32_t soff = (r * 32 + c4 * 4) * 4;   // bytes
            cp_async16(so_m + soff, mp + goff);
            cp_async16(so_b + soff, bp + goff);
        }
        cp_commit();
    };

    // Prologue: prefetch chunk (d=0, c=0) into buffer 0.
    issue(0, 0, 0);
    int buf = 0;

    for (int d = 0; d < DPT; d++) {
        float acc[NB];
#pragma unroll
        for (int i = 0; i < NB; i++) acc[i] = __int_as_float(0xff800000); // -inf

        for (int c = 0; c < NCHUNK; c++) {
            const bool has_next = !(d == DPT - 1 && c == NCHUNK - 1);
            if (has_next) {
                int nd = d, nc = c + 1;
                if (nc == NCHUNK) { nc = 0; nd = d + 1; }
                issue(nd, nc, buf ^ 1);
                asm volatile("cp.async.wait_group 1;\n");
            } else {
                asm volatile("cp.async.wait_group 0;\n");
            }
            __syncwarp();

            // Compute on `buf`: lane owns its row; 4 columns per step via
            // LDS.128; lane-rotated 16B-group order keeps LDS at BW floor.
            const uint32_t base_m = wslice + buf * (WARP_BUF_FLOATS * 4)
                                           + lane * 32 * 4;
            const uint32_t base_b = base_m + 1024 * 4;
#pragma unroll
            for (int cc = 0; cc < CHUNK / 4; cc++) {       // 8 steps of 4 cols
                const uint32_t cp = ((cc + lane) & 7) * 16;  // bytes
                u64 m01, m23, b01, b23;
                lds_v2b64(base_m + cp, m01, m23);
                lds_v2b64(base_b + cp, b01, b23);
#pragma unroll
                for (int i = 0; i < NB; i++) {
                    u64 s01 = ffma2(qq[i], m01, b01);
                    u64 s23 = ffma2(qq[i], m23, b23);
                    float a, b2, e, f;
                    unpack2(s01, a, b2);
                    unpack2(s23, e, f);
                    acc[i] = fmaxf(acc[i], fmaxf(fmaxf(a, b2), fmaxf(e, f)));
                }
            }
            __syncwarp();   // all lanes done reading before this buffer refills
            buf ^= 1;
        }

        // min over w: shfl-min within warp (32 rows), then cross-warp via smem.
#pragma unroll
        for (int i = 0; i < NB; i++) {
            float v = acc[i];
#pragma unroll
            for (int o = 16; o > 0; o >>= 1)
                v = fminf(v, __shfl_xor_sync(0xffffffffu, v, o));
            if (lane == 0) red[wid][i] = v;
        }
        __syncthreads();
        if (tid < NB) {
            float v = red[0][tid];
#pragma unroll
            for (int w = 1; w < 8; w++) v = fminf(v, red[w][tid]);
            q_s[tid] = v;
        }
        __syncthreads();
#pragma unroll
        for (int i = 0; i < NB; i++) qq[i] = pack_dup(q_s[i]);
    }

    if (tid < NB)
        out[branch * 1024 + batch0 + tid] = q_s[tid];
}

extern "C" void kernel_launch(void* const* d_in, const int* in_sizes, int n_in,
                              void* d_out, int out_size)
{
    const float* val = (const float*)d_in[0];
    const float* M1  = (const float*)d_in[1];
    const float* B1  = (const float*)d_in[2];
    const float* M2  = (const float*)d_in[3];
    const float* B2  = (const float*)d_in[4];
    float* out = (float*)d_out;

    cudaFuncSetAttribute(dpm_kernel,
                         cudaFuncAttributeMaxDynamicSharedMemorySize, SMEM_BYTES);

    dim3 grid(1024 / NB, 2);   // 64 batch tiles x 2 branches = 128 CTAs
    dpm_kernel<<<grid, 256, SMEM_BYTES>>>(val, M1, B1, M2, B2, out);
}